// round 7
// baseline (speedup 1.0000x reference)
#include <cuda_runtime.h>

// Crystalformer MHA, GB300 sm_103a. G=64, NA=64, H=8, D=64.
// Dense per-crystal edges: m = g*4096 + i*64 + j. HBM-bound (512MB `values`).
//
// Single fused kernel, one block per (g,i), 128 threads.
// Thread t owns head h = t>>4 and dims d = (t&15)*4 .. +3 (i.e. float4 at
// offset t*4 of any 512-float row-slice [8 heads x 64 dims]).
//   1. bias row aw[g,i,:,:] (2KB contiguous) -> smem.
//   2. logits: p_j = q[i,h,:] . k[j,h,:] via 16-lane butterfly; K of the
//      crystal is L2-resident (shared by the crystal's 64 adjacent blocks).
//   3. per-head softmax over j (redundant across the 16-lane group).
//   4. stream values[g,i,:,:,:] (128KB, DRAM) fused with v (L2):
//      out = sum_j w[h,j] * (v[j,h,:] + values[i,j,h,:]).
// No scratch, no flags, no multi-stream; poison overwritten directly.

#define GC 64
#define NA 64
#define NH 8
#define HD 64
#define NAH (NH * HD)   // 512

__global__ void __launch_bounds__(128)
crystal_fused_kernel(const float* __restrict__ q,
                     const float* __restrict__ k,
                     const float* __restrict__ v,
                     const float* __restrict__ aw,
                     const float* __restrict__ vals,
                     float* __restrict__ out)
{
    __shared__ float s_aw[NA * NH];   // bias row, [j][h] interleave (2 KB)
    __shared__ float sW[NH][NA];      // logits, then softmax weights (2 KB)

    const int t = threadIdx.x;
    const int h = t >> 4;             // head
    const int u = t & 15;             // lane-in-group
    const size_t gi = blockIdx.x;     // g*64 + i
    const int g = (int)(gi >> 6);

    // ---- bias row (coalesced 2KB) ----------------------------------------
    ((float4*)s_aw)[t] = __ldg((const float4*)(aw + gi * (NA * NH)) + t);

    // ---- own q fragment ---------------------------------------------------
    const float4 qf = *(const float4*)(q + gi * NAH + t * 4);
    const float* kc = k + (size_t)g * NA * NAH + t * 4;
    __syncthreads();

    // ---- logits: S[h][j] = (q.k)*scale + bias ----------------------------
    #pragma unroll 4
    for (int j = 0; j < NA; j++) {
        float4 kj = __ldg((const float4*)(kc + (size_t)j * NAH));
        float p = qf.x * kj.x + qf.y * kj.y + qf.z * kj.z + qf.w * kj.w;
        p += __shfl_xor_sync(0xFFFFFFFFu, p, 1);
        p += __shfl_xor_sync(0xFFFFFFFFu, p, 2);
        p += __shfl_xor_sync(0xFFFFFFFFu, p, 4);
        p += __shfl_xor_sync(0xFFFFFFFFu, p, 8);
        if ((j & 15) == u)
            sW[h][j] = fmaf(p, 0.125f, s_aw[j * NH + h]);
    }
    __syncthreads();

    // ---- softmax over j for head h (all 16 lanes compute identically) ----
    float mx = -1e30f;
    #pragma unroll
    for (int j = 0; j < NA; j++) mx = fmaxf(mx, sW[h][j]);
    float sum = 0.f;
    #pragma unroll
    for (int j = 0; j < NA; j++) sum += __expf(sW[h][j] - mx);
    float inv = __frcp_rn(sum);
    __syncthreads();    // everyone done reading logits before overwrite

    #pragma unroll
    for (int jj = 0; jj < 4; jj++) {
        int j = jj * 16 + u;
        sW[h][j] = __expf(sW[h][j] - mx) * inv;
    }
    __syncthreads();

    // ---- stream values (DRAM) fused with v (L2) --------------------------
    const float* vc = v + (size_t)g * NA * NAH + t * 4;
    const float* vp = vals + gi * NA * NAH + t * 4;

    float4 acc = make_float4(0.f, 0.f, 0.f, 0.f);
    #pragma unroll 8
    for (int j = 0; j < NA; j++) {
        float4 e  = __ldcs((const float4*)(vp + (size_t)j * NAH));
        float4 vj = __ldg ((const float4*)(vc + (size_t)j * NAH));
        float  w  = sW[h][j];
        acc.x = fmaf(w, vj.x + e.x, acc.x);
        acc.y = fmaf(w, vj.y + e.y, acc.y);
        acc.z = fmaf(w, vj.z + e.z, acc.z);
        acc.w = fmaf(w, vj.w + e.w, acc.w);
    }
    *(float4*)(out + gi * NAH + t * 4) = acc;
}

extern "C" void kernel_launch(void* const* d_in, const int* in_sizes, int n_in,
                              void* d_out, int out_size)
{
    const float* q    = (const float*)d_in[0];
    const float* k    = (const float*)d_in[1];
    const float* v    = (const float*)d_in[2];
    const float* aw   = (const float*)d_in[3];
    const float* vals = (const float*)d_in[4];
    // d_in[5] = edges: deterministic dense pattern, unused.

    crystal_fused_kernel<<<GC * NA, 128>>>(q, k, v, aw, vals, (float*)d_out);
}